// round 8
// baseline (speedup 1.0000x reference)
#include <cuda_runtime.h>
#include <cuda_fp16.h>

#define NN 50000
#define D  64
#define NE 800000
#define H  128
#define NTILES 391          // 128-row tiles

typedef unsigned int u32;

// Static scratch (no allocs allowed).
__device__ __align__(16) float  g_agg[NN * D];   // fp32 scatter accumulator
__device__ __align__(16) __half g_xh [NN * D];   // x in fp16 (gather source)
__device__ int g_idx_is64;

// ---- smem layout (bytes). Padded strides -> conflict-free fragment LDS. ----
#define OFF_A1  0            // [128 rows][72 halves], k=64 used   (18432 B)
#define OFF_W1T 18432        // [128 n][72 halves],   k=64 used    (18432 B)
#define OFF_W2T 36864        // [64 n][136 halves],   k=128 used   (17408 B)
#define OFF_SB1 54272        // 128 floats
#define OFF_SB2 54784        // 64 floats
#define SMEM_BYTES 55040

// ---------------------------------------------------------------------------
__device__ __forceinline__ u32 pack_h2(float lo, float hi) {
    __half2 h = __floats2half2_rn(lo, hi);     // x=lo (low half), y=hi
    return *(u32*)&h;
}
__device__ __forceinline__ void mma_f16(float* c, const u32* a, u32 b0, u32 b1) {
    asm volatile(
        "mma.sync.aligned.m16n8k16.row.col.f32.f16.f16.f32 "
        "{%0,%1,%2,%3}, {%4,%5,%6,%7}, {%8,%9}, {%0,%1,%2,%3};"
        : "+f"(c[0]), "+f"(c[1]), "+f"(c[2]), "+f"(c[3])
        : "r"(a[0]), "r"(a[1]), "r"(a[2]), "r"(a[3]), "r"(b0), "r"(b1));
}

// ---------------------------------------------------------------------------
// Kernel 1: convert x -> fp16 (g_xh). Block 0 also detects edge_index dtype
// (ids in [0,NN); an int32 buffer read as int64 packs two ids -> >= 2^32
// unless the high word is 0; P(false-pass) ~ (1/NN)^128).
// ---------------------------------------------------------------------------
__global__ void convert_kernel(const float* __restrict__ x,
                               const void* __restrict__ ei) {
    if (blockIdx.x == 0 && threadIdx.x < 128) {
        __shared__ int bad;
        if (threadIdx.x == 0) bad = 0;
        __syncthreads();
        long long v = ((const long long*)ei)[threadIdx.x];
        if (v < 0 || v >= NN) atomicOr(&bad, 1);
        __syncthreads();
        if (threadIdx.x == 0) g_idx_is64 = !bad;
    }
    int i = blockIdx.x * blockDim.x + threadIdx.x;   // one per 8 floats
    if (i < NN * D / 8) {
        const float4* src = (const float4*)x + i * 2;
        float4 a = src[0], b = src[1];
        u32 r[4] = { pack_h2(a.x, a.y), pack_h2(a.z, a.w),
                     pack_h2(b.x, b.y), pack_h2(b.z, b.w) };
        ((uint4*)g_xh)[i] = make_uint4(r[0], r[1], r[2], r[3]);
    }
}

// ---------------------------------------------------------------------------
// Kernel 2: scatter-add. 8 threads/edge; each thread gathers 8 fp16 values
// (16B LDG.128), converts to fp32, and issues two red.global.add.v4.f32.
// Gather read traffic halved vs fp32; accumulation precision kept fp32.
// ---------------------------------------------------------------------------
__global__ void scatter_kernel(const void* __restrict__ ei) {
    int idx = blockIdx.x * blockDim.x + threadIdx.x;
    if (idx >= NE * 8) return;
    int e = idx >> 3;
    int c = idx & 7;            // 8-half chunk index
    int dst_n, src_n;
    if (g_idx_is64) {
        const long long* p = (const long long*)ei;
        dst_n = (int)p[e];
        src_n = (int)p[NE + e];
    } else {
        const int* p = (const int*)ei;
        dst_n = p[e];
        src_n = p[NE + e];
    }
    uint4 hv = ((const uint4*)(g_xh + (size_t)src_n * D))[c];
    float2 f0 = __half22float2(*(__half2*)&hv.x);
    float2 f1 = __half22float2(*(__half2*)&hv.y);
    float2 f2 = __half22float2(*(__half2*)&hv.z);
    float2 f3 = __half22float2(*(__half2*)&hv.w);
    float* dst = g_agg + (size_t)dst_n * D + c * 8;
    asm volatile("red.global.add.v4.f32 [%0], {%1, %2, %3, %4};"
                 :: "l"(dst), "f"(f0.x), "f"(f0.y), "f"(f1.x), "f"(f1.y)
                 : "memory");
    asm volatile("red.global.add.v4.f32 [%0], {%1, %2, %3, %4};"
                 :: "l"(dst + 4), "f"(f2.x), "f"(f2.y), "f"(f3.x), "f"(f3.y)
                 : "memory");
}

// ---------------------------------------------------------------------------
// Kernel 3: fp16 HMMA MLP, spill-free (unchanged from R7 winner).
// ---------------------------------------------------------------------------
__global__ __launch_bounds__(256, 2)
void mlp_kernel(const float* __restrict__ x,
                const float* __restrict__ W1, const float* __restrict__ b1,
                const float* __restrict__ W2, const float* __restrict__ b2,
                const float* __restrict__ eps, float* __restrict__ out) {
    extern __shared__ char sm[];
    int tid  = threadIdx.x;
    int wid  = tid >> 5;
    int lane = tid & 31;
    int g = lane >> 2, t = lane & 3;
    int r0 = blockIdx.x * 128;
    float s = 1.0f + eps[0];

    for (int f = tid; f < 64 * H; f += 256) {
        int k = f >> 7, n = f & 127;
        *(__half*)(sm + OFF_W1T + n * 144 + k * 2) = __float2half_rn(W1[f]);
    }
    for (int f = tid; f < H * 64; f += 256) {
        int k = f >> 6, n = f & 63;
        *(__half*)(sm + OFF_W2T + n * 272 + k * 2) = __float2half_rn(W2[f]);
    }
    if (tid < 128) ((float*)(sm + OFF_SB1))[tid] = b1[tid];
    if (tid < 64)  ((float*)(sm + OFF_SB2))[tid] = b2[tid];

    // stage A1: h = (1+eps)*x + agg -> fp16, [row][k] stride 72 halves
    for (int f = tid; f < 2048; f += 256) {
        int row = f >> 4, c4 = f & 15;
        int gr = r0 + row; if (gr >= NN) gr = NN - 1;
        float4 xv = ((const float4*)x)[gr * 16 + c4];
        float4 av = ((const float4*)g_agg)[gr * 16 + c4];
        u32 p0 = pack_h2(fmaf(s, xv.x, av.x), fmaf(s, xv.y, av.y));
        u32 p1 = pack_h2(fmaf(s, xv.z, av.z), fmaf(s, xv.w, av.w));
        char* dst = sm + OFF_A1 + row * 144 + c4 * 8;
        *(u32*)dst = p0;
        *(u32*)(dst + 4) = p1;
    }
    __syncthreads();

    const float* sb1f = (const float*)(sm + OFF_SB1);
    const float* sb2f = (const float*)(sm + OFF_SB2);
    const char* Abase = sm + OFF_A1 + (16 * wid + g) * 144 + 4 * t;

    u32 a2[8][4];
#pragma unroll
    for (int half = 0; half < 2; half++) {
        float acc[8][4];
#pragma unroll
        for (int nt = 0; nt < 8; nt++) {
            int n0 = 64 * half + 8 * nt;
            float bA = sb1f[n0 + 2 * t], bB = sb1f[n0 + 2 * t + 1];
            acc[nt][0] = bA; acc[nt][1] = bB; acc[nt][2] = bA; acc[nt][3] = bB;
        }
#pragma unroll
        for (int kk = 0; kk < 4; kk++) {
            u32 aF[4];
            aF[0] = *(const u32*)(Abase + kk * 32);
            aF[1] = *(const u32*)(Abase + kk * 32 + 1152);
            aF[2] = *(const u32*)(Abase + kk * 32 + 16);
            aF[3] = *(const u32*)(Abase + kk * 32 + 1168);
#pragma unroll
            for (int nt = 0; nt < 8; nt++) {
                const char* Bb = sm + OFF_W1T + (64 * half + 8 * nt + g) * 144
                               + 4 * t + kk * 32;
                mma_f16(acc[nt], aF, *(const u32*)Bb, *(const u32*)(Bb + 16));
            }
        }
#pragma unroll
        for (int nt = 0; nt < 8; nt++) {
            float c0 = fmaxf(acc[nt][0], 0.f), c1 = fmaxf(acc[nt][1], 0.f);
            float c2 = fmaxf(acc[nt][2], 0.f), c3 = fmaxf(acc[nt][3], 0.f);
            int kk = 4 * half + (nt >> 1), hf = (nt & 1) * 2;
            a2[kk][hf]     = pack_h2(c0, c1);
            a2[kk][hf + 1] = pack_h2(c2, c3);
        }
    }

    float acc2[8][4];
#pragma unroll
    for (int nt = 0; nt < 8; nt++) {
        float bA = sb2f[8 * nt + 2 * t], bB = sb2f[8 * nt + 2 * t + 1];
        acc2[nt][0] = bA; acc2[nt][1] = bB; acc2[nt][2] = bA; acc2[nt][3] = bB;
    }
#pragma unroll
    for (int kk = 0; kk < 8; kk++) {
#pragma unroll
        for (int nt = 0; nt < 8; nt++) {
            const char* Bb = sm + OFF_W2T + (8 * nt + g) * 272 + 4 * t + kk * 32;
            mma_f16(acc2[nt], a2[kk], *(const u32*)Bb, *(const u32*)(Bb + 16));
        }
    }

    int row0 = r0 + 16 * wid + g;
#pragma unroll
    for (int nt = 0; nt < 8; nt++) {
        int col = 8 * nt + 2 * t;
        if (row0 < NN) {
            float2 v = { acc2[nt][0], acc2[nt][1] };
            *(float2*)(out + (size_t)row0 * D + col) = v;
        }
        if (row0 + 8 < NN) {
            float2 v = { acc2[nt][2], acc2[nt][3] };
            *(float2*)(out + (size_t)(row0 + 8) * D + col) = v;
        }
    }
}

// ---------------------------------------------------------------------------
extern "C" void kernel_launch(void* const* d_in, const int* in_sizes, int n_in,
                              void* d_out, int out_size) {
    const float* x   = (const float*)d_in[0];
    const void*  ei  = d_in[1];
    const float* W1  = (const float*)d_in[2];
    const float* b1  = (const float*)d_in[3];
    const float* W2  = (const float*)d_in[4];
    const float* b2  = (const float*)d_in[5];
    const float* eps = (const float*)d_in[6];
    float* out = (float*)d_out;

    // Zero accumulator via memset node (graph-capturable, no alloc).
    void* agg_ptr = nullptr;
    cudaGetSymbolAddress(&agg_ptr, g_agg);
    cudaMemsetAsync(agg_ptr, 0, (size_t)NN * D * sizeof(float), 0);

    convert_kernel<<<(NN * D / 8 + 255) / 256, 256>>>(x, ei);
    scatter_kernel<<<(NE * 8 + 255) / 256, 256>>>(ei);

    cudaFuncSetAttribute(mlp_kernel,
                         cudaFuncAttributeMaxDynamicSharedMemorySize, SMEM_BYTES);
    mlp_kernel<<<NTILES, 256, SMEM_BYTES>>>(x, W1, b1, W2, b2, eps, out);
}

// round 9
// speedup vs baseline: 1.2566x; 1.2566x over previous
#include <cuda_runtime.h>
#include <cuda_fp16.h>

#define NN 50000
#define D  64
#define NE 800000
#define H  128
#define NTILES 391          // 128-row tiles

typedef unsigned int u32;

// Static scratch (no allocs allowed).
__device__ __align__(16) float  g_agg[NN * D];      // (1+eps)*x + scatter sum
__device__ __align__(16) __half g_w1t[128 * 72];    // W1^T padded, smem image
__device__ __align__(16) __half g_w2t[64 * 136];    // W2^T padded, smem image
__device__ int g_idx_is64;

// ---- smem layout (bytes). Padded strides -> conflict-free fragment LDS. ----
#define OFF_A1  0            // [128 rows][72 halves], k=64 used   (18432 B)
#define OFF_W1T 18432        // [128 n][72 halves],   k=64 used    (18432 B)
#define OFF_W2T 36864        // [64 n][136 halves],   k=128 used   (17408 B)
#define OFF_SB1 54272        // 128 floats
#define OFF_SB2 54784        // 64 floats
#define SMEM_BYTES 55040

// ---------------------------------------------------------------------------
__device__ __forceinline__ u32 pack_h2(float lo, float hi) {
    __half2 h = __floats2half2_rn(lo, hi);     // x=lo (low half), y=hi
    return *(u32*)&h;
}
__device__ __forceinline__ void mma_f16(float* c, const u32* a, u32 b0, u32 b1) {
    asm volatile(
        "mma.sync.aligned.m16n8k16.row.col.f32.f16.f16.f32 "
        "{%0,%1,%2,%3}, {%4,%5,%6,%7}, {%8,%9}, {%0,%1,%2,%3};"
        : "+f"(c[0]), "+f"(c[1]), "+f"(c[2]), "+f"(c[3])
        : "r"(a[0]), "r"(a[1]), "r"(a[2]), "r"(a[3]), "r"(b0), "r"(b1));
}

// ---------------------------------------------------------------------------
// Kernel 1: g_agg = (1+eps)*x. Block 0 also detects edge_index dtype
// (ids in [0,NN); an int32 buffer read as int64 packs two ids -> >= 2^32
// unless the high word is 0; P(false-pass) ~ (1/NN)^128).
// ---------------------------------------------------------------------------
__global__ void init_kernel(const float* __restrict__ x,
                            const float* __restrict__ eps,
                            const void* __restrict__ ei) {
    if (blockIdx.x == 0 && threadIdx.x < 128) {
        __shared__ int bad;
        if (threadIdx.x == 0) bad = 0;
        __syncthreads();
        long long v = ((const long long*)ei)[threadIdx.x];
        if (v < 0 || v >= NN) atomicOr(&bad, 1);
        __syncthreads();
        if (threadIdx.x == 0) g_idx_is64 = !bad;
    }
    int i = blockIdx.x * blockDim.x + threadIdx.x;
    if (i < NN * D / 4) {
        float s = 1.0f + eps[0];
        float4 v = reinterpret_cast<const float4*>(x)[i];
        v.x *= s; v.y *= s; v.z *= s; v.w *= s;
        reinterpret_cast<float4*>(g_agg)[i] = v;
    }
}

// ---------------------------------------------------------------------------
// Kernel 1b: pre-transpose weights to fp16 padded global images.
// 16384 threads: i < 8192 -> W1^T[n][k] (stride 72), else W2^T[n][k] (136).
// ---------------------------------------------------------------------------
__global__ void weights_kernel(const float* __restrict__ W1,
                               const float* __restrict__ W2) {
    int i = blockIdx.x * blockDim.x + threadIdx.x;
    if (i < 64 * H) {                       // W1[k][n], k<64, n<128
        int k = i >> 7, n = i & 127;
        g_w1t[n * 72 + k] = __float2half_rn(W1[i]);
    } else {
        int j = i - 64 * H;                 // W2[k][n], k<128, n<64
        int k = j >> 6, n = j & 63;
        g_w2t[n * 136 + k] = __float2half_rn(W2[j]);
    }
}

// ---------------------------------------------------------------------------
// Kernel 2: scatter-add (R7 winner, unchanged): 16 threads/edge, contiguous
// 256B row, red.global.add.v4.f32. At the L2 atomic-throughput limit.
// ---------------------------------------------------------------------------
__global__ void scatter_kernel(const float* __restrict__ x,
                               const void* __restrict__ ei) {
    int idx = blockIdx.x * blockDim.x + threadIdx.x;
    if (idx >= NE * 16) return;
    int e = idx >> 4;
    int c = idx & 15;
    int dst_n, src_n;
    if (g_idx_is64) {
        const long long* p = (const long long*)ei;
        dst_n = (int)p[e];
        src_n = (int)p[NE + e];
    } else {
        const int* p = (const int*)ei;
        dst_n = p[e];
        src_n = p[NE + e];
    }
    float4 v = reinterpret_cast<const float4*>(x + (size_t)src_n * D)[c];
    float* dst = g_agg + (size_t)dst_n * D + c * 4;
    asm volatile("red.global.add.v4.f32 [%0], {%1, %2, %3, %4};"
                 :: "l"(dst), "f"(v.x), "f"(v.y), "f"(v.z), "f"(v.w)
                 : "memory");
}

// ---------------------------------------------------------------------------
// Kernel 3: fp16 HMMA MLP, spill-free (R7 structure). Staging simplified:
// A1 reads only g_agg (init already folded (1+eps)*x); weights copied as
// pre-transposed uint4 images.
// ---------------------------------------------------------------------------
__global__ __launch_bounds__(256, 2)
void mlp_kernel(const float* __restrict__ b1, const float* __restrict__ b2,
                float* __restrict__ out) {
    extern __shared__ char sm[];
    int tid  = threadIdx.x;
    int wid  = tid >> 5;
    int lane = tid & 31;
    int g = lane >> 2, t = lane & 3;
    int r0 = blockIdx.x * 128;

    // ---- stage weights: plain vector copies of the padded images ----
    const uint4* w1g = (const uint4*)g_w1t;
    for (int i = tid; i < 1152; i += 256) ((uint4*)(sm + OFF_W1T))[i] = w1g[i];
    const uint4* w2g = (const uint4*)g_w2t;
    for (int i = tid; i < 1088; i += 256) ((uint4*)(sm + OFF_W2T))[i] = w2g[i];
    if (tid < 128) ((float*)(sm + OFF_SB1))[tid] = b1[tid];
    if (tid < 64)  ((float*)(sm + OFF_SB2))[tid] = b2[tid];

    // ---- stage A1: h (already = (1+eps)x + agg) -> fp16, stride 72 halves ----
    for (int f = tid; f < 2048; f += 256) {
        int row = f >> 4, c4 = f & 15;
        int gr = r0 + row; if (gr >= NN) gr = NN - 1;
        float4 av = ((const float4*)g_agg)[gr * 16 + c4];
        u32 p0 = pack_h2(av.x, av.y);
        u32 p1 = pack_h2(av.z, av.w);
        char* dst = sm + OFF_A1 + row * 144 + c4 * 8;
        *(u32*)dst = p0;
        *(u32*)(dst + 4) = p1;
    }
    __syncthreads();

    const float* sb1f = (const float*)(sm + OFF_SB1);
    const float* sb2f = (const float*)(sm + OFF_SB2);
    const char* Abase = sm + OFF_A1 + (16 * wid + g) * 144 + 4 * t;

    // ---- phase 1 in two n-halves; phase-2 A fragments built in registers ----
    u32 a2[8][4];
#pragma unroll
    for (int half = 0; half < 2; half++) {
        float acc[8][4];
#pragma unroll
        for (int nt = 0; nt < 8; nt++) {
            int n0 = 64 * half + 8 * nt;
            float bA = sb1f[n0 + 2 * t], bB = sb1f[n0 + 2 * t + 1];
            acc[nt][0] = bA; acc[nt][1] = bB; acc[nt][2] = bA; acc[nt][3] = bB;
        }
#pragma unroll
        for (int kk = 0; kk < 4; kk++) {
            u32 aF[4];
            aF[0] = *(const u32*)(Abase + kk * 32);
            aF[1] = *(const u32*)(Abase + kk * 32 + 1152);
            aF[2] = *(const u32*)(Abase + kk * 32 + 16);
            aF[3] = *(const u32*)(Abase + kk * 32 + 1168);
#pragma unroll
            for (int nt = 0; nt < 8; nt++) {
                const char* Bb = sm + OFF_W1T + (64 * half + 8 * nt + g) * 144
                               + 4 * t + kk * 32;
                mma_f16(acc[nt], aF, *(const u32*)Bb, *(const u32*)(Bb + 16));
            }
        }
#pragma unroll
        for (int nt = 0; nt < 8; nt++) {
            float c0 = fmaxf(acc[nt][0], 0.f), c1 = fmaxf(acc[nt][1], 0.f);
            float c2 = fmaxf(acc[nt][2], 0.f), c3 = fmaxf(acc[nt][3], 0.f);
            int kk = 4 * half + (nt >> 1), hf = (nt & 1) * 2;
            a2[kk][hf]     = pack_h2(c0, c1);
            a2[kk][hf + 1] = pack_h2(c2, c3);
        }
    }

    // ---- phase 2 ----
    float acc2[8][4];
#pragma unroll
    for (int nt = 0; nt < 8; nt++) {
        float bA = sb2f[8 * nt + 2 * t], bB = sb2f[8 * nt + 2 * t + 1];
        acc2[nt][0] = bA; acc2[nt][1] = bB; acc2[nt][2] = bA; acc2[nt][3] = bB;
    }
#pragma unroll
    for (int kk = 0; kk < 8; kk++) {
#pragma unroll
        for (int nt = 0; nt < 8; nt++) {
            const char* Bb = sm + OFF_W2T + (8 * nt + g) * 272 + 4 * t + kk * 32;
            mma_f16(acc2[nt], a2[kk], *(const u32*)Bb, *(const u32*)(Bb + 16));
        }
    }

    // ---- store (rows 16w+g and 16w+g+8, cols 8nt+2t) ----
    int row0 = r0 + 16 * wid + g;
#pragma unroll
    for (int nt = 0; nt < 8; nt++) {
        int col = 8 * nt + 2 * t;
        if (row0 < NN) {
            float2 v = { acc2[nt][0], acc2[nt][1] };
            *(float2*)(out + (size_t)row0 * D + col) = v;
        }
        if (row0 + 8 < NN) {
            float2 v = { acc2[nt][2], acc2[nt][3] };
            *(float2*)(out + (size_t)(row0 + 8) * D + col) = v;
        }
    }
}

// ---------------------------------------------------------------------------
extern "C" void kernel_launch(void* const* d_in, const int* in_sizes, int n_in,
                              void* d_out, int out_size) {
    const float* x   = (const float*)d_in[0];
    const void*  ei  = d_in[1];
    const float* W1  = (const float*)d_in[2];
    const float* b1  = (const float*)d_in[3];
    const float* W2  = (const float*)d_in[4];
    const float* b2  = (const float*)d_in[5];
    const float* eps = (const float*)d_in[6];
    float* out = (float*)d_out;

    init_kernel<<<(NN * D / 4 + 255) / 256, 256>>>(x, eps, ei);
    weights_kernel<<<64, 256>>>(W1, W2);
    scatter_kernel<<<(NE * 16 + 255) / 256, 256>>>(x, ei);

    cudaFuncSetAttribute(mlp_kernel,
                         cudaFuncAttributeMaxDynamicSharedMemorySize, SMEM_BYTES);
    mlp_kernel<<<NTILES, 256, SMEM_BYTES>>>(b1, b2, out);
}

// round 13
// speedup vs baseline: 1.2922x; 1.0283x over previous
#include <cuda_runtime.h>
#include <cuda_fp16.h>

#define NN 50000
#define D  64
#define NE 800000
#define H  128
#define NTILES 391          // 128-row tiles

typedef unsigned int u32;

// Static scratch (no allocs allowed).
__device__ __align__(16) float  g_agg[NN * D];      // (1+eps)*x + scatter sum
__device__ __align__(16) __half g_xh [NN * D];      // x in fp16 (gather source)
__device__ __align__(16) __half g_w1t[128 * 72];    // W1^T padded, smem image
__device__ __align__(16) __half g_w2t[64 * 136];    // W2^T padded, smem image
__device__ int g_idx_is64;

// ---- smem layout (bytes). Padded strides -> conflict-free fragment LDS. ----
#define OFF_A1  0            // [128 rows][72 halves], k=64 used   (18432 B)
#define OFF_W1T 18432        // [128 n][72 halves],   k=64 used    (18432 B)
#define OFF_W2T 36864        // [64 n][136 halves],   k=128 used   (17408 B)
#define OFF_SB1 54272        // 128 floats
#define OFF_SB2 54784        // 64 floats
#define SMEM_BYTES 55040

// ---------------------------------------------------------------------------
__device__ __forceinline__ u32 pack_h2(float lo, float hi) {
    __half2 h = __floats2half2_rn(lo, hi);     // x=lo (low half), y=hi
    return *(u32*)&h;
}
__device__ __forceinline__ void mma_f16(float* c, const u32* a, u32 b0, u32 b1) {
    asm volatile(
        "mma.sync.aligned.m16n8k16.row.col.f32.f16.f16.f32 "
        "{%0,%1,%2,%3}, {%4,%5,%6,%7}, {%8,%9}, {%0,%1,%2,%3};"
        : "+f"(c[0]), "+f"(c[1]), "+f"(c[2]), "+f"(c[3])
        : "r"(a[0]), "r"(a[1]), "r"(a[2]), "r"(a[3]), "r"(b0), "r"(b1));
}

// ---------------------------------------------------------------------------
// Kernel 1: g_agg = (1+eps)*x  AND  g_xh = fp16(x), one pass.
// Block 0 also detects edge_index dtype (ids in [0,NN); an int32 buffer read
// as int64 packs two ids -> >= 2^32 unless high word 0; P ~ (1/NN)^128).
// ---------------------------------------------------------------------------
__global__ void init_kernel(const float* __restrict__ x,
                            const float* __restrict__ eps,
                            const void* __restrict__ ei) {
    if (blockIdx.x == 0 && threadIdx.x < 128) {
        __shared__ int bad;
        if (threadIdx.x == 0) bad = 0;
        __syncthreads();
        long long v = ((const long long*)ei)[threadIdx.x];
        if (v < 0 || v >= NN) atomicOr(&bad, 1);
        __syncthreads();
        if (threadIdx.x == 0) g_idx_is64 = !bad;
    }
    int i = blockIdx.x * blockDim.x + threadIdx.x;
    if (i < NN * D / 4) {
        float s = 1.0f + eps[0];
        float4 v = reinterpret_cast<const float4*>(x)[i];
        ((uint2*)g_xh)[i] = make_uint2(pack_h2(v.x, v.y), pack_h2(v.z, v.w));
        v.x *= s; v.y *= s; v.z *= s; v.w *= s;
        reinterpret_cast<float4*>(g_agg)[i] = v;
    }
}

// ---------------------------------------------------------------------------
// Kernel 1b: pre-transpose weights to fp16 padded global images.
// ---------------------------------------------------------------------------
__global__ void weights_kernel(const float* __restrict__ W1,
                               const float* __restrict__ W2) {
    int i = blockIdx.x * blockDim.x + threadIdx.x;
    if (i < 64 * H) {                       // W1[k][n], k<64, n<128
        int k = i >> 7, n = i & 127;
        g_w1t[n * 72 + k] = __float2half_rn(W1[i]);
    } else {
        int j = i - 64 * H;                 // W2[k][n], k<128, n<64
        int k = j >> 6, n = j & 63;
        g_w2t[n * 136 + k] = __float2half_rn(W2[j]);
    }
}

// ---------------------------------------------------------------------------
// Kernel 2: scatter-add. SAME mapping as the R7 winner (16 threads/edge, one
// red.global.add.v4.f32 per thread); only the gather shrinks: LDG.64 of 4
// fp16 values from g_xh instead of LDG.128 fp32. L2 traffic 410 -> 307 MB.
// ---------------------------------------------------------------------------
__global__ void scatter_kernel(const void* __restrict__ ei) {
    int idx = blockIdx.x * blockDim.x + threadIdx.x;
    if (idx >= NE * 16) return;
    int e = idx >> 4;
    int c = idx & 15;
    int dst_n, src_n;
    if (g_idx_is64) {
        const long long* p = (const long long*)ei;
        dst_n = (int)p[e];
        src_n = (int)p[NE + e];
    } else {
        const int* p = (const int*)ei;
        dst_n = p[e];
        src_n = p[NE + e];
    }
    uint2 hv = ((const uint2*)(g_xh + (size_t)src_n * D))[c];
    float2 f0 = __half22float2(*(__half2*)&hv.x);
    float2 f1 = __half22float2(*(__half2*)&hv.y);
    float* dst = g_agg + (size_t)dst_n * D + c * 4;
    asm volatile("red.global.add.v4.f32 [%0], {%1, %2, %3, %4};"
                 :: "l"(dst), "f"(f0.x), "f"(f0.y), "f"(f1.x), "f"(f1.y)
                 : "memory");
}

// ---------------------------------------------------------------------------
// Kernel 3: fp16 HMMA MLP. Phase 2 now runs in two n-halves (peak acc regs
// 16 instead of 32) so the kernel fits 3 blocks/SM -> grid 391 is ONE wave
// with 24 warps/SM of latency hiding.
// ---------------------------------------------------------------------------
__global__ __launch_bounds__(256, 3)
void mlp_kernel(const float* __restrict__ b1, const float* __restrict__ b2,
                float* __restrict__ out) {
    extern __shared__ char sm[];
    int tid  = threadIdx.x;
    int wid  = tid >> 5;
    int lane = tid & 31;
    int g = lane >> 2, t = lane & 3;
    int r0 = blockIdx.x * 128;

    // ---- stage weights: vector copies of the padded images ----
    const uint4* w1g = (const uint4*)g_w1t;
    for (int i = tid; i < 1152; i += 256) ((uint4*)(sm + OFF_W1T))[i] = w1g[i];
    const uint4* w2g = (const uint4*)g_w2t;
    for (int i = tid; i < 1088; i += 256) ((uint4*)(sm + OFF_W2T))[i] = w2g[i];
    if (tid < 128) ((float*)(sm + OFF_SB1))[tid] = b1[tid];
    if (tid < 64)  ((float*)(sm + OFF_SB2))[tid] = b2[tid];

    // ---- stage A1: h -> fp16, [row][k] stride 72 halves ----
    for (int f = tid; f < 2048; f += 256) {
        int row = f >> 4, c4 = f & 15;
        int gr = r0 + row; if (gr >= NN) gr = NN - 1;
        float4 av = ((const float4*)g_agg)[gr * 16 + c4];
        char* dst = sm + OFF_A1 + row * 144 + c4 * 8;
        *(u32*)dst       = pack_h2(av.x, av.y);
        *(u32*)(dst + 4) = pack_h2(av.z, av.w);
    }
    __syncthreads();

    const float* sb1f = (const float*)(sm + OFF_SB1);
    const float* sb2f = (const float*)(sm + OFF_SB2);
    const char* Abase = sm + OFF_A1 + (16 * wid + g) * 144 + 4 * t;

    // ---- phase 1 in two n-halves; phase-2 A fragments built in registers ----
    u32 a2[8][4];
#pragma unroll
    for (int half = 0; half < 2; half++) {
        float acc[8][4];
#pragma unroll
        for (int nt = 0; nt < 8; nt++) {
            int n0 = 64 * half + 8 * nt;
            float bA = sb1f[n0 + 2 * t], bB = sb1f[n0 + 2 * t + 1];
            acc[nt][0] = bA; acc[nt][1] = bB; acc[nt][2] = bA; acc[nt][3] = bB;
        }
#pragma unroll
        for (int kk = 0; kk < 4; kk++) {
            u32 aF[4];
            aF[0] = *(const u32*)(Abase + kk * 32);
            aF[1] = *(const u32*)(Abase + kk * 32 + 1152);
            aF[2] = *(const u32*)(Abase + kk * 32 + 16);
            aF[3] = *(const u32*)(Abase + kk * 32 + 1168);
#pragma unroll
            for (int nt = 0; nt < 8; nt++) {
                const char* Bb = sm + OFF_W1T + (64 * half + 8 * nt + g) * 144
                               + 4 * t + kk * 32;
                mma_f16(acc[nt], aF, *(const u32*)Bb, *(const u32*)(Bb + 16));
            }
        }
#pragma unroll
        for (int nt = 0; nt < 8; nt++) {
            float c0 = fmaxf(acc[nt][0], 0.f), c1 = fmaxf(acc[nt][1], 0.f);
            float c2 = fmaxf(acc[nt][2], 0.f), c3 = fmaxf(acc[nt][3], 0.f);
            int kk = 4 * half + (nt >> 1), hf = (nt & 1) * 2;
            a2[kk][hf]     = pack_h2(c0, c1);
            a2[kk][hf + 1] = pack_h2(c2, c3);
        }
    }

    // ---- phase 2 in two n-halves (16 acc regs peak) ----
    int row0 = r0 + 16 * wid + g;
#pragma unroll
    for (int nh = 0; nh < 2; nh++) {
        float acc2[4][4];
#pragma unroll
        for (int nt = 0; nt < 4; nt++) {
            int n0 = 32 * nh + 8 * nt;
            float bA = sb2f[n0 + 2 * t], bB = sb2f[n0 + 2 * t + 1];
            acc2[nt][0] = bA; acc2[nt][1] = bB; acc2[nt][2] = bA; acc2[nt][3] = bB;
        }
#pragma unroll
        for (int kk = 0; kk < 8; kk++) {
#pragma unroll
            for (int nt = 0; nt < 4; nt++) {
                const char* Bb = sm + OFF_W2T + (32 * nh + 8 * nt + g) * 272
                               + 4 * t + kk * 32;
                mma_f16(acc2[nt], a2[kk], *(const u32*)Bb, *(const u32*)(Bb + 16));
            }
        }
#pragma unroll
        for (int nt = 0; nt < 4; nt++) {
            int col = 32 * nh + 8 * nt + 2 * t;
            if (row0 < NN) {
                float2 v = { acc2[nt][0], acc2[nt][1] };
                *(float2*)(out + (size_t)row0 * D + col) = v;
            }
            if (row0 + 8 < NN) {
                float2 v = { acc2[nt][2], acc2[nt][3] };
                *(float2*)(out + (size_t)(row0 + 8) * D + col) = v;
            }
        }
    }
}

// ---------------------------------------------------------------------------
extern "C" void kernel_launch(void* const* d_in, const int* in_sizes, int n_in,
                              void* d_out, int out_size) {
    const float* x   = (const float*)d_in[0];
    const void*  ei  = d_in[1];
    const float* W1  = (const float*)d_in[2];
    const float* b1  = (const float*)d_in[3];
    const float* W2  = (const float*)d_in[4];
    const float* b2  = (const float*)d_in[5];
    const float* eps = (const float*)d_in[6];
    float* out = (float*)d_out;

    init_kernel<<<(NN * D / 4 + 255) / 256, 256>>>(x, eps, ei);
    weights_kernel<<<64, 256>>>(W1, W2);
    scatter_kernel<<<(NE * 16 + 255) / 256, 256>>>(ei);

    cudaFuncSetAttribute(mlp_kernel,
                         cudaFuncAttributeMaxDynamicSharedMemorySize, SMEM_BYTES);
    mlp_kernel<<<NTILES, 256, SMEM_BYTES>>>(b1, b2, out);
}